// round 5
// baseline (speedup 1.0000x reference)
#include <cuda_runtime.h>

#define EPS 1e-5f

typedef unsigned long long u64;

// ---------------- f32x2 helpers ----------------
__device__ __forceinline__ void fma2(u64& d, u64 a, u64 b) {
    asm volatile("fma.rn.f32x2 %0, %1, %2, %0;" : "+l"(d) : "l"(a), "l"(b));
}
__device__ __forceinline__ u64 dup2(float x) {
    u64 r; asm("mov.b64 %0, {%1, %1};" : "=l"(r) : "f"(x)); return r;
}
__device__ __forceinline__ float2 unpack2(u64 v) {
    float2 r; asm("mov.b64 {%0, %1}, %2;" : "=f"(r.x), "=f"(r.y) : "l"(v)); return r;
}

// ---------------- scratch (device globals; no allocation allowed) ----------------
__device__ float g_xn[4 * 144 * 4096];        // normalized input
__device__ float g_wint[144 * 64];            // w_in transposed [c][o]
__device__ float g_w1tt[9 * 64 * 64];         // w1 as [drds][o2][o]
__device__ float g_w2tt[64 * 576];            // w2 as [o3][rs*64+o2]
__device__ float g_sin[64], g_tin[64];
__device__ float g_s1[64],  g_t1[64];
__device__ float g_s2[64],  g_t2[64];
__device__ float g_sout[144], g_tout[144];
__device__ float g_A[16384 * 25 * 64];        // post GEMM1+BN+ReLU  [pos][k][o]
__device__ float g_A1[16384 * 9 * 64];        // post conv1+BN+ReLU  [pos][rs][o2]
__device__ float g_B2[16384 * 64];            // post conv2+BN+ReLU  [pos][o3]

// ---------------- weight transpose + BN folding ----------------
__global__ void prep_kernel(const float* __restrict__ w_in,
                            const float* __restrict__ gin, const float* __restrict__ bin,
                            const float* __restrict__ min_, const float* __restrict__ vin,
                            const float* __restrict__ w1,
                            const float* __restrict__ g1, const float* __restrict__ b1,
                            const float* __restrict__ m1, const float* __restrict__ v1,
                            const float* __restrict__ w2,
                            const float* __restrict__ g2, const float* __restrict__ b2,
                            const float* __restrict__ m2, const float* __restrict__ v2,
                            const float* __restrict__ go, const float* __restrict__ bo,
                            const float* __restrict__ mo, const float* __restrict__ vo)
{
    int i = blockIdx.x * blockDim.x + threadIdx.x;   // grid covers 36864
    if (i < 36864) {
        // w1tt[drds][o2][o] = w1[o2][o][drds]
        int drds = i >> 12; int r1 = i & 4095;
        int o2 = r1 >> 6; int o = r1 & 63;
        g_w1tt[i] = w1[(o2 * 64 + o) * 9 + drds];
        // w2tt[o3][rs*64+o2] = w2[o3][o2][rs]
        int o3 = i / 576; int r2 = i - o3 * 576;
        int rs = r2 >> 6; int o2b = r2 & 63;
        g_w2tt[i] = w2[(o3 * 64 + o2b) * 9 + rs];
    }
    if (i < 9216) { int c = i >> 6; int o = i & 63; g_wint[i] = w_in[o * 144 + c]; }
    if (i < 64) {
        float s;
        s = gin[i] * rsqrtf(vin[i] + EPS); g_sin[i] = s; g_tin[i] = bin[i] - min_[i] * s;
        s = g1[i]  * rsqrtf(v1[i]  + EPS); g_s1[i]  = s; g_t1[i]  = b1[i]  - m1[i]  * s;
        s = g2[i]  * rsqrtf(v2[i]  + EPS); g_s2[i]  = s; g_t2[i]  = b2[i]  - m2[i]  * s;
    }
    if (i < 144) {
        float s = go[i] * rsqrtf(vo[i] + EPS); g_sout[i] = s; g_tout[i] = bo[i] - mo[i] * s;
    }
}

// ---------------- L2 normalize over channels ----------------
__global__ void normalize_kernel(const float* __restrict__ x)
{
    int p = blockIdx.x * 256 + threadIdx.x;          // 16384 positions
    int b = p >> 12, hw = p & 4095;
    const float* xb = x + (size_t)b * 589824 + hw;   // 144*4096
    float ss = 0.f;
    #pragma unroll 4
    for (int c = 0; c < 144; c++) { float v = xb[c * 4096]; ss += v * v; }
    float inv = 1.0f / fmaxf(sqrtf(ss), 1e-12f);
    float* yb = g_xn + (size_t)b * 589824 + hw;
    #pragma unroll 4
    for (int c = 0; c < 144; c++) yb[c * 4096] = xb[c * 4096] * inv;
}

// ---------------- GEMM1: z[p,k,o] = sum_c w_in[o,c]*y[c,k,p]; BN+ReLU ----------------
// CTA = 4 positions. smem: y[144][25][4] (57.6KB) + wint (36.9KB) -> 2 CTA/SM.
// Thread owns all 4 p (2 f32x2 pairs) and 4 channels (oc, +16, +32, +48).
// Warp g owns k = g + 8*kk. y loads = broadcast LDS.128 (1 wf per c,k).
__global__ void __launch_bounds__(256) gemm1_kernel()
{
    extern __shared__ float sm[];
    float* y   = sm;                                 // 14400
    float* wsm = sm + 14400;                         // 9216
    int pos0 = blockIdx.x << 2;
    int b = pos0 >> 12, hw0 = pos0 & 4095;
    int h = hw0 >> 6, w0 = hw0 & 63;
    int tid = threadIdx.x;
    const float* xb = g_xn + (size_t)b * 589824;

    // stage w_in^T
    #pragma unroll
    for (int j = 0; j < 9; j++) {
        int idx = tid + j * 256;                     // 2304 float4 = 9216 floats
        ((float4*)wsm)[idx] = ((const float4*)g_wint)[idx];
    }
    // build y tile: y[(c*25+k)*4 + p] = patch(c,k,p) * center(c,p)
    for (int u = tid; u < 3600; u += 256) {
        int c = u / 25, k = u - c * 25;
        int kh = k / 5, kw = k - kh * 5;
        int gh = h + kh - 2;
        bool rok = ((unsigned)gh < 64u);
        const float* xc = xb + c * 4096;
        float4 out;
        float ctr0 = xc[(h << 6) + w0 + 0], ctr1 = xc[(h << 6) + w0 + 1];
        float ctr2 = xc[(h << 6) + w0 + 2], ctr3 = xc[(h << 6) + w0 + 3];
        int gw0 = w0 + kw - 2;
        float v0 = (rok && (unsigned)(gw0 + 0) < 64u) ? xc[(gh << 6) + gw0 + 0] : 0.f;
        float v1 = (rok && (unsigned)(gw0 + 1) < 64u) ? xc[(gh << 6) + gw0 + 1] : 0.f;
        float v2 = (rok && (unsigned)(gw0 + 2) < 64u) ? xc[(gh << 6) + gw0 + 2] : 0.f;
        float v3 = (rok && (unsigned)(gw0 + 3) < 64u) ? xc[(gh << 6) + gw0 + 3] : 0.f;
        out.x = v0 * ctr0; out.y = v1 * ctr1; out.z = v2 * ctr2; out.w = v3 * ctr3;
        ((float4*)y)[u] = out;
    }
    __syncthreads();

    int lane = tid & 31, g = tid >> 5;
    int oc = lane & 15;                              // channels oc + 16j
    int nk = (g == 0) ? 4 : 3;                       // k = g + 8*kk
    u64 acc[4][4][2];                                // [kk][ch][pair]
    #pragma unroll
    for (int kk = 0; kk < 4; kk++)
        #pragma unroll
        for (int j = 0; j < 4; j++) { acc[kk][j][0] = 0; acc[kk][j][1] = 0; }

    for (int c = 0; c < 144; c++) {
        u64 wd[4];
        #pragma unroll
        for (int j = 0; j < 4; j++) wd[j] = dup2(wsm[(c << 6) + oc + (j << 4)]);
        #pragma unroll
        for (int kk = 0; kk < 4; kk++) {
            if (kk < nk) {
                int k = g + (kk << 3);
                ulonglong2 yv = *(const ulonglong2*)&y[(c * 25 + k) << 2];
                #pragma unroll
                for (int j = 0; j < 4; j++) {
                    fma2(acc[kk][j][0], yv.x, wd[j]);
                    fma2(acc[kk][j][1], yv.y, wd[j]);
                }
            }
        }
    }

    #pragma unroll
    for (int kk = 0; kk < 4; kk++) {
        if (kk < nk) {
            int k = g + (kk << 3);
            #pragma unroll
            for (int j = 0; j < 4; j++) {
                int o = oc + (j << 4);
                float s = g_sin[o], t = g_tin[o];
                #pragma unroll
                for (int q = 0; q < 2; q++) {
                    float2 v = unpack2(acc[kk][j][q]);
                    g_A[(((pos0 + 2 * q)     * 25 + k) << 6) + o] = fmaxf(v.x * s + t, 0.f);
                    g_A[(((pos0 + 2 * q + 1) * 25 + k) << 6) + o] = fmaxf(v.y * s + t, 0.f);
                }
            }
        }
    }
}

// ---------------- Conv1: 3x3 VALID over 5x5 grid, 64->64; BN+ReLU ----------------
// CTA = 8 positions. smem: A[8][25][64] (51.2KB) + w slice [64][68] (17.4KB) -> 3 CTA/SM.
// Warp g owns position g; half-warps split the 9 rs units 5/4;
// each thread 4 channels (oc, +16, +32, +48). f32x2 along contraction o, LDS.128.
__global__ void __launch_bounds__(256, 3) conv1_kernel()
{
    extern __shared__ float sm[];
    float* As  = sm;                                 // 12800
    float* ws1 = sm + 12800;                         // 64*68 = 4352
    int pos0 = blockIdx.x << 3;
    int tid = threadIdx.x;

    const float4* Ag = (const float4*)(g_A + ((size_t)pos0 * 1600));
    for (int i = tid; i < 3200; i += 256) ((float4*)As)[i] = Ag[i];

    int lane = tid & 31, g = tid >> 5;
    int oc = lane & 15;
    int grp = lane >> 4;                             // 0: rs 0..4, 1: rs 5..8
    int nu = grp ? 4 : 5;
    int abase = g * 1600;                            // warp g owns position g

    int roff[5];
    #pragma unroll
    for (int i = 0; i < 5; i++) {
        int rs = grp ? 5 + i : i;
        int r = rs / 3, s = rs - r * 3;
        roff[i] = r * 5 + s;
    }
    u64 acc[5][4];
    #pragma unroll
    for (int i = 0; i < 5; i++)
        #pragma unroll
        for (int j = 0; j < 4; j++) acc[i][j] = 0;

    for (int drds = 0; drds < 9; drds++) {
        __syncthreads();                             // As ready (iter0) / ws1 drained
        const float4* wsrc = (const float4*)(g_w1tt + (drds << 12));
        #pragma unroll
        for (int j2 = 0; j2 < 4; j2++) {
            int idx = tid + (j2 << 8);               // 1024 float4
            int row = idx >> 4, col = idx & 15;
            *(float4*)&ws1[row * 68 + (col << 2)] = wsrc[idx];
        }
        __syncthreads();

        int dr = drds / 3, ds = drds - dr * 3;
        int shift = dr * 5 + ds;
        int base[5];
        #pragma unroll
        for (int i = 0; i < 5; i++)
            base[i] = abase + ((roff[i] + shift) << 6);

        for (int o = 0; o < 64; o += 4) {
            ulonglong2 wv[4];
            #pragma unroll
            for (int j = 0; j < 4; j++)
                wv[j] = *(const ulonglong2*)&ws1[(oc + (j << 4)) * 68 + o];
            #pragma unroll
            for (int i = 0; i < 5; i++) {
                if (i < nu) {
                    ulonglong2 a = *(const ulonglong2*)&As[base[i] + o];
                    #pragma unroll
                    for (int j = 0; j < 4; j++) {
                        fma2(acc[i][j], a.x, wv[j].x);
                        fma2(acc[i][j], a.y, wv[j].y);
                    }
                }
            }
        }
    }

    #pragma unroll
    for (int i = 0; i < 5; i++) {
        if (i < nu) {
            int rs = grp ? 5 + i : i;
            int obase = ((pos0 + g) * 9 + rs) << 6;
            #pragma unroll
            for (int j = 0; j < 4; j++) {
                int o = oc + (j << 4);
                float2 v = unpack2(acc[i][j]);
                g_A1[obase + o] = fmaxf((v.x + v.y) * g_s1[o] + g_t1[o], 0.f);
            }
        }
    }
}

// ---------------- Conv2: 3x3 -> 1x1, 64->64; BN+ReLU ----------------
// CTA = 32 positions. smem: A1[32][576] (73.7KB) + w chunk [64][68] (17.4KB) -> 2 CTA/SM.
// f32x2 along contraction j, LDS.128 chunks of 4.
__global__ void __launch_bounds__(256) conv2_kernel()
{
    extern __shared__ float sm[];
    float* A1s = sm;                                 // 18432
    float* ws2 = sm + 18432;                         // 4352
    int pos0 = blockIdx.x << 5;
    int tid = threadIdx.x;

    const float4* src = (const float4*)(g_A1 + ((size_t)pos0 * 576));
    for (int i = tid; i < 4608; i += 256) ((float4*)A1s)[i] = src[i];

    int o3b = tid & 31, g = tid >> 5;                // warp g owns p = g+8i
    u64 acc[4][2];
    #pragma unroll
    for (int i = 0; i < 4; i++) { acc[i][0] = 0; acc[i][1] = 0; }

    for (int jc = 0; jc < 9; jc++) {
        __syncthreads();
        #pragma unroll
        for (int j2 = 0; j2 < 16; j2++) {
            int idx = tid + (j2 << 8);
            ws2[(idx >> 6) * 68 + (idx & 63)] = g_w2tt[(idx >> 6) * 576 + (jc << 6) + (idx & 63)];
        }
        __syncthreads();

        int jbase = jc << 6;
        for (int jj = 0; jj < 64; jj += 4) {
            ulonglong2 wlo = *(const ulonglong2*)&ws2[o3b * 68 + jj];
            ulonglong2 whi = *(const ulonglong2*)&ws2[(o3b + 32) * 68 + jj];
            #pragma unroll
            for (int i = 0; i < 4; i++) {
                int p = g + (i << 3);
                ulonglong2 a = *(const ulonglong2*)&A1s[p * 576 + jbase + jj];
                fma2(acc[i][0], a.x, wlo.x);
                fma2(acc[i][0], a.y, wlo.y);
                fma2(acc[i][1], a.x, whi.x);
                fma2(acc[i][1], a.y, whi.y);
            }
        }
    }

    float sa = g_s2[o3b], ta = g_t2[o3b], sb = g_s2[o3b + 32], tb = g_t2[o3b + 32];
    #pragma unroll
    for (int i = 0; i < 4; i++) {
        int p = pos0 + g + (i << 3);
        float2 va = unpack2(acc[i][0]);
        float2 vb = unpack2(acc[i][1]);
        g_B2[(p << 6) + o3b]      = fmaxf((va.x + va.y) * sa + ta, 0.f);
        g_B2[(p << 6) + o3b + 32] = fmaxf((vb.x + vb.y) * sb + tb, 0.f);
    }
}

// ---------------- GEMM out: 64->144, BN (no ReLU) ----------------
// CTA = 64 positions. f32x2 packed along output channels; broadcast LDS.128 weights.
__global__ void __launch_bounds__(256) gemmout_kernel(const float* __restrict__ w_out,
                                                      float* __restrict__ out)
{
    extern __shared__ float sm[];                    // 4160 + 9216 floats
    float* B2t = sm;
    float* ws  = sm + 4160;
    int pos0 = blockIdx.x << 6;
    int tid = threadIdx.x;

    for (int idx = tid; idx < 4096; idx += 256) {
        int p = idx >> 6, cm = idx & 63;
        B2t[cm * 65 + p] = g_B2[(pos0 << 6) + idx];
    }
    for (int idx = tid; idx < 9216; idx += 256) {
        int oc = idx >> 6, cm = idx & 63;
        ws[cm * 144 + oc] = w_out[idx];              // w_out[oc][cm]
    }
    __syncthreads();

    int pl = tid & 63, ocg = tid >> 6;               // ocg block of 36 oc
    u64 acc[18];
    #pragma unroll
    for (int j = 0; j < 18; j++) acc[j] = 0;

    for (int cm = 0; cm < 64; cm++) {
        u64 bv = dup2(B2t[cm * 65 + pl]);
        const ulonglong2* wp = (const ulonglong2*)&ws[cm * 144 + ocg * 36];
        #pragma unroll
        for (int j = 0; j < 9; j++) {
            ulonglong2 w = wp[j];
            fma2(acc[2 * j],     w.x, bv);
            fma2(acc[2 * j + 1], w.y, bv);
        }
    }

    int b = pos0 >> 12, hw0 = pos0 & 4095;
    float* op = out + (size_t)b * 589824 + hw0 + pl;
    #pragma unroll
    for (int j = 0; j < 18; j++) {
        int oc0 = ocg * 36 + 2 * j;
        float2 v = unpack2(acc[j]);
        op[(size_t)oc0 * 4096]       = v.x * g_sout[oc0]     + g_tout[oc0];
        op[(size_t)(oc0 + 1) * 4096] = v.y * g_sout[oc0 + 1] + g_tout[oc0 + 1];
    }
}

// ---------------- launch ----------------
extern "C" void kernel_launch(void* const* d_in, const int* in_sizes, int n_in,
                              void* d_out, int out_size)
{
    (void)in_sizes; (void)n_in; (void)out_size;
    const float* x     = (const float*)d_in[0];
    const float* w_in  = (const float*)d_in[1];
    const float* gin   = (const float*)d_in[2];
    const float* bin   = (const float*)d_in[3];
    const float* min_  = (const float*)d_in[4];
    const float* vin   = (const float*)d_in[5];
    const float* w1    = (const float*)d_in[6];
    const float* g1    = (const float*)d_in[7];
    const float* b1    = (const float*)d_in[8];
    const float* m1    = (const float*)d_in[9];
    const float* v1    = (const float*)d_in[10];
    const float* w2    = (const float*)d_in[11];
    const float* g2    = (const float*)d_in[12];
    const float* b2    = (const float*)d_in[13];
    const float* m2    = (const float*)d_in[14];
    const float* v2    = (const float*)d_in[15];
    const float* w_out = (const float*)d_in[16];
    const float* go    = (const float*)d_in[17];
    const float* bo    = (const float*)d_in[18];
    const float* mo    = (const float*)d_in[19];
    const float* vo    = (const float*)d_in[20];
    float* out = (float*)d_out;

    cudaFuncSetAttribute(gemm1_kernel,   cudaFuncAttributeMaxDynamicSharedMemorySize, 94464);
    cudaFuncSetAttribute(conv1_kernel,   cudaFuncAttributeMaxDynamicSharedMemorySize, 68608);
    cudaFuncSetAttribute(conv2_kernel,   cudaFuncAttributeMaxDynamicSharedMemorySize, 91136);
    cudaFuncSetAttribute(gemmout_kernel, cudaFuncAttributeMaxDynamicSharedMemorySize, 53504);

    prep_kernel<<<144, 256>>>(w_in, gin, bin, min_, vin,
                              w1, g1, b1, m1, v1,
                              w2, g2, b2, m2, v2,
                              go, bo, mo, vo);
    normalize_kernel<<<64, 256>>>(x);
    gemm1_kernel<<<4096, 256, 94464>>>();
    conv1_kernel<<<2048, 256, 68608>>>();
    conv2_kernel<<<512, 256, 91136>>>();
    gemmout_kernel<<<256, 256, 53504>>>(w_out, out);
}

// round 6
// speedup vs baseline: 1.3690x; 1.3690x over previous
#include <cuda_runtime.h>

#define EPS 1e-5f

typedef unsigned long long u64;

// ---------------- f32x2 helpers ----------------
__device__ __forceinline__ void fma2(u64& d, u64 a, u64 b) {
    asm volatile("fma.rn.f32x2 %0, %1, %2, %0;" : "+l"(d) : "l"(a), "l"(b));
}
__device__ __forceinline__ u64 dup2(float x) {
    u64 r; asm("mov.b64 %0, {%1, %1};" : "=l"(r) : "f"(x)); return r;
}
__device__ __forceinline__ float2 unpack2(u64 v) {
    float2 r; asm("mov.b64 {%0, %1}, %2;" : "=f"(r.x), "=f"(r.y) : "l"(v)); return r;
}

// ---------------- scratch (device globals; no allocation allowed) ----------------
__device__ float g_xn[4 * 144 * 4096];        // normalized input
__device__ float g_wint[144 * 64];            // w_in transposed [c][o]
__device__ float g_w1oc[9 * 64 * 64];         // w1 as [drds][o][c]
__device__ float g_w2tt[64 * 576];            // w2 as [o3][rs*64+o2]
__device__ float g_sin[64], g_tin[64];
__device__ float g_s1[64],  g_t1[64];
__device__ float g_s2[64],  g_t2[64];
__device__ float g_sout[144], g_tout[144];
__device__ float g_A[16384 * 25 * 64];        // post GEMM1+BN+ReLU  [pos][k][o]
__device__ float g_A1[16384 * 9 * 64];        // post conv1+BN+ReLU  [pos][rs][o2]
__device__ float g_B2[16384 * 64];            // post conv2+BN+ReLU  [pos][o3]

// ---------------- weight transpose + BN folding ----------------
__global__ void prep_kernel(const float* __restrict__ w_in,
                            const float* __restrict__ gin, const float* __restrict__ bin,
                            const float* __restrict__ min_, const float* __restrict__ vin,
                            const float* __restrict__ w1,
                            const float* __restrict__ g1, const float* __restrict__ b1,
                            const float* __restrict__ m1, const float* __restrict__ v1,
                            const float* __restrict__ w2,
                            const float* __restrict__ g2, const float* __restrict__ b2,
                            const float* __restrict__ m2, const float* __restrict__ v2,
                            const float* __restrict__ go, const float* __restrict__ bo,
                            const float* __restrict__ mo, const float* __restrict__ vo)
{
    int i = blockIdx.x * blockDim.x + threadIdx.x;   // grid covers 36864
    if (i < 36864) {
        // w1oc[drds][o][c] = w1[c][o][drds]
        int drds = i >> 12; int r1 = i & 4095;
        int o = r1 >> 6; int c = r1 & 63;
        g_w1oc[i] = w1[(c * 64 + o) * 9 + drds];
        // w2tt[o3][rs*64+o2] = w2[o3][o2][rs]
        int o3 = i / 576; int r2 = i - o3 * 576;
        int rs = r2 >> 6; int o2b = r2 & 63;
        g_w2tt[i] = w2[(o3 * 64 + o2b) * 9 + rs];
    }
    if (i < 9216) { int c = i >> 6; int o = i & 63; g_wint[i] = w_in[o * 144 + c]; }
    if (i < 64) {
        float s;
        s = gin[i] * rsqrtf(vin[i] + EPS); g_sin[i] = s; g_tin[i] = bin[i] - min_[i] * s;
        s = g1[i]  * rsqrtf(v1[i]  + EPS); g_s1[i]  = s; g_t1[i]  = b1[i]  - m1[i]  * s;
        s = g2[i]  * rsqrtf(v2[i]  + EPS); g_s2[i]  = s; g_t2[i]  = b2[i]  - m2[i]  * s;
    }
    if (i < 144) {
        float s = go[i] * rsqrtf(vo[i] + EPS); g_sout[i] = s; g_tout[i] = bo[i] - mo[i] * s;
    }
}

// ---------------- L2 normalize over channels ----------------
__global__ void normalize_kernel(const float* __restrict__ x)
{
    int p = blockIdx.x * 256 + threadIdx.x;          // 16384 positions
    int b = p >> 12, hw = p & 4095;
    const float* xb = x + (size_t)b * 589824 + hw;   // 144*4096
    float ss = 0.f;
    #pragma unroll 4
    for (int c = 0; c < 144; c++) { float v = xb[c * 4096]; ss += v * v; }
    float inv = 1.0f / fmaxf(sqrtf(ss), 1e-12f);
    float* yb = g_xn + (size_t)b * 589824 + hw;
    #pragma unroll 4
    for (int c = 0; c < 144; c++) yb[c * 4096] = xb[c * 4096] * inv;
}

// ---------------- GEMM1: z[p,k,o] = sum_c w_in[o,c]*y[c,k,p]; BN+ReLU ----------------
// CTA = 4 positions. smem: y[144][25][4] (57.6KB) + wint (36.9KB) -> 2 CTA/SM.
// Half-warps split the contraction (c even / c odd); lane oc owns 4 contiguous
// channels 4*oc..4*oc+3; warp g owns k = g + 8*kk. f32x2 packed along p.
// Epilogue: shfl-xor(16) reduce across c-halves.
__global__ void __launch_bounds__(256, 2) gemm1_kernel()
{
    extern __shared__ float sm[];
    float* y   = sm;                                 // 14400
    float* wsm = sm + 14400;                         // 9216
    int pos0 = blockIdx.x << 2;
    int b = pos0 >> 12, hw0 = pos0 & 4095;
    int h0 = hw0 >> 6, w0 = hw0 & 63;
    int tid = threadIdx.x;
    const float* xb = g_xn + (size_t)b * 589824;

    // stage w_in^T  [c][o]
    #pragma unroll
    for (int j = 0; j < 9; j++) {
        int idx = tid + j * 256;                     // 2304 float4 = 9216 floats
        ((float4*)wsm)[idx] = ((const float4*)g_wint)[idx];
    }
    // build y tile: y[(c*25+k)*4 + p] = patch(c,k,p) * center(c,p)
    for (int u = tid; u < 3600; u += 256) {
        int c = u / 25, k = u - c * 25;
        int kh = k / 5, kw = k - kh * 5;
        int gh = h0 + kh - 2;
        bool rok = ((unsigned)gh < 64u);
        const float* xc = xb + c * 4096;
        float4 out;
        float ctr0 = xc[(h0 << 6) + w0 + 0], ctr1 = xc[(h0 << 6) + w0 + 1];
        float ctr2 = xc[(h0 << 6) + w0 + 2], ctr3 = xc[(h0 << 6) + w0 + 3];
        int gw0 = w0 + kw - 2;
        float v0 = (rok && (unsigned)(gw0 + 0) < 64u) ? xc[(gh << 6) + gw0 + 0] : 0.f;
        float v1 = (rok && (unsigned)(gw0 + 1) < 64u) ? xc[(gh << 6) + gw0 + 1] : 0.f;
        float v2 = (rok && (unsigned)(gw0 + 2) < 64u) ? xc[(gh << 6) + gw0 + 2] : 0.f;
        float v3 = (rok && (unsigned)(gw0 + 3) < 64u) ? xc[(gh << 6) + gw0 + 3] : 0.f;
        out.x = v0 * ctr0; out.y = v1 * ctr1; out.z = v2 * ctr2; out.w = v3 * ctr3;
        ((float4*)y)[u] = out;
    }
    __syncthreads();

    int lane = tid & 31, g = tid >> 5;
    int oc = lane & 15;                              // channels 4oc..4oc+3
    int h  = lane >> 4;                              // c-parity half
    int nk = (g == 0) ? 4 : 3;                       // k = g + 8*kk
    u64 acc[4][4][2];                                // [kk][ch][pair]
    #pragma unroll
    for (int kk = 0; kk < 4; kk++)
        #pragma unroll
        for (int j = 0; j < 4; j++) { acc[kk][j][0] = 0; acc[kk][j][1] = 0; }

    const float* wrow = wsm + (h << 6) + (oc << 2);  // + ci*128
    const float* yrow = y + ((h * 25 + g) << 2);     // + ci*200, + kk*32

    #pragma unroll 2
    for (int ci = 0; ci < 72; ci++) {
        float4 w4 = *(const float4*)(wrow + (ci << 7));
        u64 wd0 = dup2(w4.x), wd1 = dup2(w4.y), wd2 = dup2(w4.z), wd3 = dup2(w4.w);
        const float* yc = yrow + ci * 200;
        #pragma unroll
        for (int kk = 0; kk < 4; kk++) {
            if (kk < nk) {
                ulonglong2 yv = *(const ulonglong2*)(yc + (kk << 5));
                fma2(acc[kk][0][0], yv.x, wd0); fma2(acc[kk][0][1], yv.y, wd0);
                fma2(acc[kk][1][0], yv.x, wd1); fma2(acc[kk][1][1], yv.y, wd1);
                fma2(acc[kk][2][0], yv.x, wd2); fma2(acc[kk][2][1], yv.y, wd2);
                fma2(acc[kk][3][0], yv.x, wd3); fma2(acc[kk][3][1], yv.y, wd3);
            }
        }
    }

    // epilogue: reduce across c-halves, write pair h (positions 2h, 2h+1)
    float4 s4 = *(const float4*)&g_sin[oc << 2];
    float4 t4 = *(const float4*)&g_tin[oc << 2];
    #pragma unroll
    for (int kk = 0; kk < 4; kk++) {
        if (kk < nk) {
            int k = g + (kk << 3);
            float2 sel[4];
            #pragma unroll
            for (int j = 0; j < 4; j++) {
                u64 p0 = acc[kk][j][0], p1 = acc[kk][j][1];
                u64 q0 = __shfl_xor_sync(0xffffffffu, p0, 16);
                u64 q1 = __shfl_xor_sync(0xffffffffu, p1, 16);
                float2 a0 = unpack2(p0), b0 = unpack2(q0);
                float2 a1 = unpack2(p1), b1 = unpack2(q1);
                float2 s0 = make_float2(a0.x + b0.x, a0.y + b0.y);
                float2 s1 = make_float2(a1.x + b1.x, a1.y + b1.y);
                sel[j] = h ? s1 : s0;
            }
            float4 r0, r1;
            r0.x = fmaxf(sel[0].x * s4.x + t4.x, 0.f);
            r0.y = fmaxf(sel[1].x * s4.y + t4.y, 0.f);
            r0.z = fmaxf(sel[2].x * s4.z + t4.z, 0.f);
            r0.w = fmaxf(sel[3].x * s4.w + t4.w, 0.f);
            r1.x = fmaxf(sel[0].y * s4.x + t4.x, 0.f);
            r1.y = fmaxf(sel[1].y * s4.y + t4.y, 0.f);
            r1.z = fmaxf(sel[2].y * s4.z + t4.z, 0.f);
            r1.w = fmaxf(sel[3].y * s4.w + t4.w, 0.f);
            *(float4*)&g_A[(((size_t)(pos0 + 2 * h)     * 25 + k) << 6) + (oc << 2)] = r0;
            *(float4*)&g_A[(((size_t)(pos0 + 2 * h + 1) * 25 + k) << 6) + (oc << 2)] = r1;
        }
    }
}

// ---------------- Conv1: 3x3 VALID over 5x5 grid, 64->64; BN+ReLU ----------------
// CTA = 8 positions (4 position-pairs q). smem: As interleaved [q][k][opair][4]
// (12864 floats) + w [o][c] (4096 floats) = 67.8KB -> 2 CTA/SM.
// Warp g: q = g&3 (positions 2q, 2q+1); half-warp picks rs quarter {3,2,2,2}.
// Lane oc = lane&15 owns channels 4oc..4oc+3. f32x2 packed along position pair;
// one broadcast LDS.128 feeds 2 o's x 2 positions.
__global__ void __launch_bounds__(256, 2) conv1_kernel()
{
    extern __shared__ float sm[];
    float* As = sm;                                  // 4 * 3216 = 12864
    float* ws = sm + 12864;                          // 4096 [o][c]
    int pos0 = blockIdx.x << 3;
    int tid = threadIdx.x;

    // stage As: As[q*3216 + k*128 + op*4 + {o0p0,o0p1,o1p0,o1p1}]
    for (int u = tid; u < 3200; u += 256) {
        int pq = u / 800;
        int rem = u - pq * 800;
        int k = rem >> 5, op = rem & 31;
        const float* src = g_A + (((size_t)(pos0 + 2 * pq) * 25 + k) << 6) + (op << 1);
        float2 v0 = *(const float2*)src;             // pos 2pq   (o, o+1)
        float2 v1 = *(const float2*)(src + 1600);    // pos 2pq+1 (o, o+1)
        *(float4*)&As[pq * 3216 + (k << 7) + (op << 2)] = make_float4(v0.x, v1.x, v0.y, v1.y);
    }

    int lane = tid & 31, g = tid >> 5;
    int oc = lane & 15;
    int q = g & 3;
    int quarter = ((g >> 2) << 1) + (lane >> 4);     // 0..3
    int rs0 = (quarter == 0) ? 0 : 2 * quarter + 1;  // 0,3,5,7
    int nrs = (quarter == 0) ? 3 : 2;
    int roff[3];
    #pragma unroll
    for (int i = 0; i < 3; i++) {
        int rs = rs0 + i;
        roff[i] = (rs / 3) * 5 + rs % 3;
    }

    u64 acc[3][4];
    #pragma unroll
    for (int i = 0; i < 3; i++)
        #pragma unroll
        for (int j = 0; j < 4; j++) acc[i][j] = 0;

    const float* wrow = ws + (oc << 2);

    for (int drds = 0; drds < 9; drds++) {
        __syncthreads();
        const float4* wsrc = (const float4*)(g_w1oc + (drds << 12));
        #pragma unroll
        for (int j2 = 0; j2 < 4; j2++) {
            int idx = tid + (j2 << 8);               // 1024 float4 = 4096 floats
            ((float4*)ws)[idx] = wsrc[idx];
        }
        __syncthreads();

        int dr = drds / 3, ds = drds - dr * 3;
        int shift = dr * 5 + ds;
        int base[3];
        #pragma unroll
        for (int i = 0; i < 3; i++)
            base[i] = q * 3216 + ((roff[i] + shift) << 7);

        #pragma unroll 2
        for (int op = 0; op < 32; op++) {
            float4 we = *(const float4*)(wrow + (op << 7));       // o = 2op
            float4 wo = *(const float4*)(wrow + (op << 7) + 64);  // o = 2op+1
            u64 we0 = dup2(we.x), we1 = dup2(we.y), we2 = dup2(we.z), we3 = dup2(we.w);
            u64 wo0 = dup2(wo.x), wo1 = dup2(wo.y), wo2 = dup2(wo.z), wo3 = dup2(wo.w);
            #pragma unroll
            for (int i = 0; i < 3; i++) {
                if (i < nrs) {
                    ulonglong2 a = *(const ulonglong2*)&As[base[i] + (op << 2)];
                    fma2(acc[i][0], a.x, we0); fma2(acc[i][1], a.x, we1);
                    fma2(acc[i][2], a.x, we2); fma2(acc[i][3], a.x, we3);
                    fma2(acc[i][0], a.y, wo0); fma2(acc[i][1], a.y, wo1);
                    fma2(acc[i][2], a.y, wo2); fma2(acc[i][3], a.y, wo3);
                }
            }
        }
    }

    float4 s4 = *(const float4*)&g_s1[oc << 2];
    float4 t4 = *(const float4*)&g_t1[oc << 2];
    #pragma unroll
    for (int i = 0; i < 3; i++) {
        if (i < nrs) {
            int rs = rs0 + i;
            float2 v0 = unpack2(acc[i][0]);
            float2 v1 = unpack2(acc[i][1]);
            float2 v2 = unpack2(acc[i][2]);
            float2 v3 = unpack2(acc[i][3]);
            float4 r0, r1;
            r0.x = fmaxf(v0.x * s4.x + t4.x, 0.f);
            r0.y = fmaxf(v1.x * s4.y + t4.y, 0.f);
            r0.z = fmaxf(v2.x * s4.z + t4.z, 0.f);
            r0.w = fmaxf(v3.x * s4.w + t4.w, 0.f);
            r1.x = fmaxf(v0.y * s4.x + t4.x, 0.f);
            r1.y = fmaxf(v1.y * s4.y + t4.y, 0.f);
            r1.z = fmaxf(v2.y * s4.z + t4.z, 0.f);
            r1.w = fmaxf(v3.y * s4.w + t4.w, 0.f);
            *(float4*)&g_A1[(((size_t)(pos0 + 2 * q)     * 9 + rs) << 6) + (oc << 2)] = r0;
            *(float4*)&g_A1[(((size_t)(pos0 + 2 * q + 1) * 9 + rs) << 6) + (oc << 2)] = r1;
        }
    }
}

// ---------------- Conv2: 3x3 -> 1x1, 64->64; BN+ReLU ----------------
// CTA = 32 positions. smem: A1[32][576] (73.7KB) + w chunk [64][68] (17.4KB) -> 2 CTA/SM.
// f32x2 along contraction j, LDS.128 chunks of 4.
__global__ void __launch_bounds__(256) conv2_kernel()
{
    extern __shared__ float sm[];
    float* A1s = sm;                                 // 18432
    float* ws2 = sm + 18432;                         // 4352
    int pos0 = blockIdx.x << 5;
    int tid = threadIdx.x;

    const float4* src = (const float4*)(g_A1 + ((size_t)pos0 * 576));
    for (int i = tid; i < 4608; i += 256) ((float4*)A1s)[i] = src[i];

    int o3b = tid & 31, g = tid >> 5;                // warp g owns p = g+8i
    u64 acc[4][2];
    #pragma unroll
    for (int i = 0; i < 4; i++) { acc[i][0] = 0; acc[i][1] = 0; }

    for (int jc = 0; jc < 9; jc++) {
        __syncthreads();
        #pragma unroll
        for (int j2 = 0; j2 < 16; j2++) {
            int idx = tid + (j2 << 8);
            ws2[(idx >> 6) * 68 + (idx & 63)] = g_w2tt[(idx >> 6) * 576 + (jc << 6) + (idx & 63)];
        }
        __syncthreads();

        int jbase = jc << 6;
        for (int jj = 0; jj < 64; jj += 4) {
            ulonglong2 wlo = *(const ulonglong2*)&ws2[o3b * 68 + jj];
            ulonglong2 whi = *(const ulonglong2*)&ws2[(o3b + 32) * 68 + jj];
            #pragma unroll
            for (int i = 0; i < 4; i++) {
                int p = g + (i << 3);
                ulonglong2 a = *(const ulonglong2*)&A1s[p * 576 + jbase + jj];
                fma2(acc[i][0], a.x, wlo.x);
                fma2(acc[i][0], a.y, wlo.y);
                fma2(acc[i][1], a.x, whi.x);
                fma2(acc[i][1], a.y, whi.y);
            }
        }
    }

    float sa = g_s2[o3b], ta = g_t2[o3b], sb = g_s2[o3b + 32], tb = g_t2[o3b + 32];
    #pragma unroll
    for (int i = 0; i < 4; i++) {
        int p = pos0 + g + (i << 3);
        float2 va = unpack2(acc[i][0]);
        float2 vb = unpack2(acc[i][1]);
        g_B2[(p << 6) + o3b]      = fmaxf((va.x + va.y) * sa + ta, 0.f);
        g_B2[(p << 6) + o3b + 32] = fmaxf((vb.x + vb.y) * sb + tb, 0.f);
    }
}

// ---------------- GEMM out: 64->144, BN (no ReLU) ----------------
// CTA = 64 positions. f32x2 packed along output channels; broadcast LDS.128 weights.
__global__ void __launch_bounds__(256) gemmout_kernel(const float* __restrict__ w_out,
                                                      float* __restrict__ out)
{
    extern __shared__ float sm[];                    // 4160 + 9216 floats
    float* B2t = sm;
    float* ws  = sm + 4160;
    int pos0 = blockIdx.x << 6;
    int tid = threadIdx.x;

    for (int idx = tid; idx < 4096; idx += 256) {
        int p = idx >> 6, cm = idx & 63;
        B2t[cm * 65 + p] = g_B2[(pos0 << 6) + idx];
    }
    for (int idx = tid; idx < 9216; idx += 256) {
        int oc = idx >> 6, cm = idx & 63;
        ws[cm * 144 + oc] = w_out[idx];              // w_out[oc][cm]
    }
    __syncthreads();

    int pl = tid & 63, ocg = tid >> 6;               // ocg block of 36 oc
    u64 acc[18];
    #pragma unroll
    for (int j = 0; j < 18; j++) acc[j] = 0;

    for (int cm = 0; cm < 64; cm++) {
        u64 bv = dup2(B2t[cm * 65 + pl]);
        const ulonglong2* wp = (const ulonglong2*)&ws[cm * 144 + ocg * 36];
        #pragma unroll
        for (int j = 0; j < 9; j++) {
            ulonglong2 w = wp[j];
            fma2(acc[2 * j],     w.x, bv);
            fma2(acc[2 * j + 1], w.y, bv);
        }
    }

    int b = pos0 >> 12, hw0 = pos0 & 4095;
    float* op = out + (size_t)b * 589824 + hw0 + pl;
    #pragma unroll
    for (int j = 0; j < 18; j++) {
        int oc0 = ocg * 36 + 2 * j;
        float2 v = unpack2(acc[j]);
        op[(size_t)oc0 * 4096]       = v.x * g_sout[oc0]     + g_tout[oc0];
        op[(size_t)(oc0 + 1) * 4096] = v.y * g_sout[oc0 + 1] + g_tout[oc0 + 1];
    }
}

// ---------------- launch ----------------
extern "C" void kernel_launch(void* const* d_in, const int* in_sizes, int n_in,
                              void* d_out, int out_size)
{
    (void)in_sizes; (void)n_in; (void)out_size;
    const float* x     = (const float*)d_in[0];
    const float* w_in  = (const float*)d_in[1];
    const float* gin   = (const float*)d_in[2];
    const float* bin   = (const float*)d_in[3];
    const float* min_  = (const float*)d_in[4];
    const float* vin   = (const float*)d_in[5];
    const float* w1    = (const float*)d_in[6];
    const float* g1    = (const float*)d_in[7];
    const float* b1    = (const float*)d_in[8];
    const float* m1    = (const float*)d_in[9];
    const float* v1    = (const float*)d_in[10];
    const float* w2    = (const float*)d_in[11];
    const float* g2    = (const float*)d_in[12];
    const float* b2    = (const float*)d_in[13];
    const float* m2    = (const float*)d_in[14];
    const float* v2    = (const float*)d_in[15];
    const float* w_out = (const float*)d_in[16];
    const float* go    = (const float*)d_in[17];
    const float* bo    = (const float*)d_in[18];
    const float* mo    = (const float*)d_in[19];
    const float* vo    = (const float*)d_in[20];
    float* out = (float*)d_out;

    cudaFuncSetAttribute(gemm1_kernel,   cudaFuncAttributeMaxDynamicSharedMemorySize, 94464);
    cudaFuncSetAttribute(conv1_kernel,   cudaFuncAttributeMaxDynamicSharedMemorySize, 67840);
    cudaFuncSetAttribute(conv2_kernel,   cudaFuncAttributeMaxDynamicSharedMemorySize, 91136);
    cudaFuncSetAttribute(gemmout_kernel, cudaFuncAttributeMaxDynamicSharedMemorySize, 53504);

    prep_kernel<<<144, 256>>>(w_in, gin, bin, min_, vin,
                              w1, g1, b1, m1, v1,
                              w2, g2, b2, m2, v2,
                              go, bo, mo, vo);
    normalize_kernel<<<64, 256>>>(x);
    gemm1_kernel<<<4096, 256, 94464>>>();
    conv1_kernel<<<2048, 256, 67840>>>();
    conv2_kernel<<<512, 256, 91136>>>();
    gemmout_kernel<<<256, 256, 53504>>>(w_out, out);
}

// round 7
// speedup vs baseline: 1.6454x; 1.2019x over previous
#include <cuda_runtime.h>

#define EPS 1e-5f

typedef unsigned long long u64;

// ---------------- f32x2 helpers ----------------
__device__ __forceinline__ void fma2(u64& d, u64 a, u64 b) {
    asm volatile("fma.rn.f32x2 %0, %1, %2, %0;" : "+l"(d) : "l"(a), "l"(b));
}
__device__ __forceinline__ u64 dup2(float x) {
    u64 r; asm("mov.b64 %0, {%1, %1};" : "=l"(r) : "f"(x)); return r;
}
__device__ __forceinline__ float2 unpack2(u64 v) {
    float2 r; asm("mov.b64 {%0, %1}, %2;" : "=f"(r.x), "=f"(r.y) : "l"(v)); return r;
}

// ---------------- scratch (device globals; no allocation allowed) ----------------
__device__ float g_xn[4 * 144 * 4096];        // normalized input
__device__ float g_wint[144 * 64];            // w_in transposed [c][o]
__device__ float g_w1oc[9 * 64 * 64];         // w1 as [drds][o][c]
__device__ float g_w2tt[64 * 576];            // w2 as [o3][rs*64+o2]
__device__ float g_sin[64], g_tin[64];
__device__ float g_s1[64],  g_t1[64];
__device__ float g_s2[64],  g_t2[64];
__device__ float g_sout[144], g_tout[144];
__device__ float g_A[16384 * 25 * 64];        // post GEMM1+BN+ReLU  [pos][k][o]
__device__ float g_A1[16384 * 9 * 64];        // post conv1+BN+ReLU  [pos][rs][o2]
__device__ float g_B2[16384 * 64];            // post conv2+BN+ReLU  [pos][o3]

// ---------------- weight transpose + BN folding ----------------
__global__ void prep_kernel(const float* __restrict__ w_in,
                            const float* __restrict__ gin, const float* __restrict__ bin,
                            const float* __restrict__ min_, const float* __restrict__ vin,
                            const float* __restrict__ w1,
                            const float* __restrict__ g1, const float* __restrict__ b1,
                            const float* __restrict__ m1, const float* __restrict__ v1,
                            const float* __restrict__ w2,
                            const float* __restrict__ g2, const float* __restrict__ b2,
                            const float* __restrict__ m2, const float* __restrict__ v2,
                            const float* __restrict__ go, const float* __restrict__ bo,
                            const float* __restrict__ mo, const float* __restrict__ vo)
{
    int i = blockIdx.x * blockDim.x + threadIdx.x;   // grid covers 36864
    if (i < 36864) {
        // w1oc[drds][o][c] = w1[c][o][drds]
        int drds = i >> 12; int r1 = i & 4095;
        int o = r1 >> 6; int c = r1 & 63;
        g_w1oc[i] = w1[(c * 64 + o) * 9 + drds];
        // w2tt[o3][rs*64+o2] = w2[o3][o2][rs]
        int o3 = i / 576; int r2 = i - o3 * 576;
        int rs = r2 >> 6; int o2b = r2 & 63;
        g_w2tt[i] = w2[(o3 * 64 + o2b) * 9 + rs];
    }
    if (i < 9216) { int c = i >> 6; int o = i & 63; g_wint[i] = w_in[o * 144 + c]; }
    if (i < 64) {
        float s;
        s = gin[i] * rsqrtf(vin[i] + EPS); g_sin[i] = s; g_tin[i] = bin[i] - min_[i] * s;
        s = g1[i]  * rsqrtf(v1[i]  + EPS); g_s1[i]  = s; g_t1[i]  = b1[i]  - m1[i]  * s;
        s = g2[i]  * rsqrtf(v2[i]  + EPS); g_s2[i]  = s; g_t2[i]  = b2[i]  - m2[i]  * s;
    }
    if (i < 144) {
        float s = go[i] * rsqrtf(vo[i] + EPS); g_sout[i] = s; g_tout[i] = bo[i] - mo[i] * s;
    }
}

// ---------------- L2 normalize over channels ----------------
__global__ void normalize_kernel(const float* __restrict__ x)
{
    int p = blockIdx.x * 256 + threadIdx.x;          // 16384 positions
    int b = p >> 12, hw = p & 4095;
    const float* xb = x + (size_t)b * 589824 + hw;   // 144*4096
    float ss = 0.f;
    #pragma unroll 4
    for (int c = 0; c < 144; c++) { float v = xb[c * 4096]; ss += v * v; }
    float inv = 1.0f / fmaxf(sqrtf(ss), 1e-12f);
    float* yb = g_xn + (size_t)b * 589824 + hw;
    #pragma unroll 4
    for (int c = 0; c < 144; c++) yb[c * 4096] = xb[c * 4096] * inv;
}

// ---------------- GEMM1 (mirror-symmetric): only k=12..24 computed ----------------
// z[o,k,p] = sum_c w[o,c]*xn[c,p+dk]*xn[c,p]  is symmetric under
// (p,k) <-> (p+dk, 24-k); BN+ReLU elementwise => A[p][k] = A[p+dk][24-k].
// Each CTA (4 positions) computes k in {12..24} and writes self + mirror partner;
// entries whose partner is out-of-bounds get the constant relu(t_o).
// CTA = 4 positions. smem: y[144][13][4] (30KB) + wint (36.9KB) -> 3 CTA/SM.
// Half-warps split contraction (c parity); lane oc owns channels 4oc..4oc+3;
// warp g owns k = 12+g and 20+g (g<5). f32x2 packed along p; shfl-reduce epilogue.
__global__ void __launch_bounds__(256) gemm1_kernel()
{
    extern __shared__ float sm[];
    float* y   = sm;                                 // 7488
    float* wsm = sm + 7488;                          // 9216
    int pos0 = blockIdx.x << 2;
    int b = pos0 >> 12, hw0 = pos0 & 4095;
    int h0 = hw0 >> 6, w0 = hw0 & 63;
    int tid = threadIdx.x;
    const float* xb = g_xn + (size_t)b * 589824;

    // stage w_in^T  [c][o]
    #pragma unroll
    for (int j = 0; j < 9; j++) {
        int idx = tid + j * 256;                     // 2304 float4 = 9216 floats
        ((float4*)wsm)[idx] = ((const float4*)g_wint)[idx];
    }
    // build y tile for k=12..24: y[(c*13 + (k-12))*4 + p]
    for (int u = tid; u < 1872; u += 256) {
        int c = u / 13, kt = u - c * 13;
        int k = kt + 12;
        int kh = k / 5, kw = k - kh * 5;
        int gh = h0 + kh - 2;
        bool rok = ((unsigned)gh < 64u);
        const float* xc = xb + c * 4096;
        float4 out;
        float ctr0 = xc[(h0 << 6) + w0 + 0], ctr1 = xc[(h0 << 6) + w0 + 1];
        float ctr2 = xc[(h0 << 6) + w0 + 2], ctr3 = xc[(h0 << 6) + w0 + 3];
        int gw0 = w0 + kw - 2;
        float v0 = (rok && (unsigned)(gw0 + 0) < 64u) ? xc[(gh << 6) + gw0 + 0] : 0.f;
        float v1 = (rok && (unsigned)(gw0 + 1) < 64u) ? xc[(gh << 6) + gw0 + 1] : 0.f;
        float v2 = (rok && (unsigned)(gw0 + 2) < 64u) ? xc[(gh << 6) + gw0 + 2] : 0.f;
        float v3 = (rok && (unsigned)(gw0 + 3) < 64u) ? xc[(gh << 6) + gw0 + 3] : 0.f;
        out.x = v0 * ctr0; out.y = v1 * ctr1; out.z = v2 * ctr2; out.w = v3 * ctr3;
        ((float4*)y)[u] = out;
    }
    __syncthreads();

    int lane = tid & 31, g = tid >> 5;
    int oc = lane & 15;                              // channels 4oc..4oc+3
    int h  = lane >> 4;                              // c-parity half
    int nk = (g < 5) ? 2 : 1;                        // k = 12 + g + 8*kk
    u64 acc[2][4][2];                                // [kk][ch][pair]
    #pragma unroll
    for (int kk = 0; kk < 2; kk++)
        #pragma unroll
        for (int j = 0; j < 4; j++) { acc[kk][j][0] = 0; acc[kk][j][1] = 0; }

    const float* wrow = wsm + (h << 6) + (oc << 2);  // + ci*128
    const float* yrow = y + ((h * 13 + g) << 2);     // + ci*104, + kk*32

    #pragma unroll 2
    for (int ci = 0; ci < 72; ci++) {
        float4 w4 = *(const float4*)(wrow + (ci << 7));
        u64 wd0 = dup2(w4.x), wd1 = dup2(w4.y), wd2 = dup2(w4.z), wd3 = dup2(w4.w);
        const float* yc = yrow + ci * 104;
        #pragma unroll
        for (int kk = 0; kk < 2; kk++) {
            if (kk < nk) {
                ulonglong2 yv = *(const ulonglong2*)(yc + (kk << 5));
                fma2(acc[kk][0][0], yv.x, wd0); fma2(acc[kk][0][1], yv.y, wd0);
                fma2(acc[kk][1][0], yv.x, wd1); fma2(acc[kk][1][1], yv.y, wd1);
                fma2(acc[kk][2][0], yv.x, wd2); fma2(acc[kk][2][1], yv.y, wd2);
                fma2(acc[kk][3][0], yv.x, wd3); fma2(acc[kk][3][1], yv.y, wd3);
            }
        }
    }

    // epilogue: reduce across c-halves; write self slot, mirror-partner slot,
    // and the OOB-partner constant relu(t).
    float4 s4 = *(const float4*)&g_sin[oc << 2];
    float4 t4 = *(const float4*)&g_tin[oc << 2];
    float4 cst;
    cst.x = fmaxf(t4.x, 0.f); cst.y = fmaxf(t4.y, 0.f);
    cst.z = fmaxf(t4.z, 0.f); cst.w = fmaxf(t4.w, 0.f);

    #pragma unroll
    for (int kk = 0; kk < 2; kk++) {
        if (kk < nk) {
            int k = 12 + g + (kk << 3);
            float2 sel[4];
            #pragma unroll
            for (int j = 0; j < 4; j++) {
                u64 p0 = acc[kk][j][0], p1 = acc[kk][j][1];
                u64 q0 = __shfl_xor_sync(0xffffffffu, p0, 16);
                u64 q1 = __shfl_xor_sync(0xffffffffu, p1, 16);
                float2 a0 = unpack2(p0), b0 = unpack2(q0);
                float2 a1 = unpack2(p1), b1 = unpack2(q1);
                float2 s0 = make_float2(a0.x + b0.x, a0.y + b0.y);
                float2 s1 = make_float2(a1.x + b1.x, a1.y + b1.y);
                sel[j] = h ? s1 : s0;
            }
            float4 r[2];
            r[0].x = fmaxf(sel[0].x * s4.x + t4.x, 0.f);
            r[0].y = fmaxf(sel[1].x * s4.y + t4.y, 0.f);
            r[0].z = fmaxf(sel[2].x * s4.z + t4.z, 0.f);
            r[0].w = fmaxf(sel[3].x * s4.w + t4.w, 0.f);
            r[1].x = fmaxf(sel[0].y * s4.x + t4.x, 0.f);
            r[1].y = fmaxf(sel[1].y * s4.y + t4.y, 0.f);
            r[1].z = fmaxf(sel[2].y * s4.z + t4.z, 0.f);
            r[1].w = fmaxf(sel[3].y * s4.w + t4.w, 0.f);

            int kh = k / 5, kw = k - kh * 5;
            int dh = kh - 2, dw = kw - 2;
            int mk = 24 - k;
            #pragma unroll
            for (int e = 0; e < 2; e++) {
                int poff = (h << 1) + e;
                int p = pos0 + poff;
                *(float4*)&g_A[(((size_t)p * 25 + k) << 6) + (oc << 2)] = r[e];
                if (k != 12) {
                    int ww = w0 + poff;
                    int qh = h0 + dh, qw = ww + dw;
                    if ((unsigned)qh < 64u && (unsigned)qw < 64u) {
                        int q = (b << 12) + (qh << 6) + qw;
                        *(float4*)&g_A[(((size_t)q * 25 + mk) << 6) + (oc << 2)] = r[e];
                    }
                    int rh = h0 - dh, rw = ww - dw;
                    if (!((unsigned)rh < 64u && (unsigned)rw < 64u)) {
                        *(float4*)&g_A[(((size_t)p * 25 + mk) << 6) + (oc << 2)] = cst;
                    }
                }
            }
        }
    }
}

// ---------------- Conv1: 3x3 VALID over 5x5 grid, 64->64; BN+ReLU ----------------
// CTA = 8 positions (4 position-pairs q). smem: As interleaved [q][k][opair][4]
// (12864 floats) + w [o][c] (4096 floats) = 67.8KB -> 2 CTA/SM.
__global__ void __launch_bounds__(256, 2) conv1_kernel()
{
    extern __shared__ float sm[];
    float* As = sm;                                  // 4 * 3216 = 12864
    float* ws = sm + 12864;                          // 4096 [o][c]
    int pos0 = blockIdx.x << 3;
    int tid = threadIdx.x;

    // stage As: As[q*3216 + k*128 + op*4 + {o0p0,o0p1,o1p0,o1p1}]
    for (int u = tid; u < 3200; u += 256) {
        int pq = u / 800;
        int rem = u - pq * 800;
        int k = rem >> 5, op = rem & 31;
        const float* src = g_A + (((size_t)(pos0 + 2 * pq) * 25 + k) << 6) + (op << 1);
        float2 v0 = *(const float2*)src;             // pos 2pq   (o, o+1)
        float2 v1 = *(const float2*)(src + 1600);    // pos 2pq+1 (o, o+1)
        *(float4*)&As[pq * 3216 + (k << 7) + (op << 2)] = make_float4(v0.x, v1.x, v0.y, v1.y);
    }

    int lane = tid & 31, g = tid >> 5;
    int oc = lane & 15;
    int q = g & 3;
    int quarter = ((g >> 2) << 1) + (lane >> 4);     // 0..3
    int rs0 = (quarter == 0) ? 0 : 2 * quarter + 1;  // 0,3,5,7
    int nrs = (quarter == 0) ? 3 : 2;
    int roff[3];
    #pragma unroll
    for (int i = 0; i < 3; i++) {
        int rs = rs0 + i;
        roff[i] = (rs / 3) * 5 + rs % 3;
    }

    u64 acc[3][4];
    #pragma unroll
    for (int i = 0; i < 3; i++)
        #pragma unroll
        for (int j = 0; j < 4; j++) acc[i][j] = 0;

    const float* wrow = ws + (oc << 2);

    for (int drds = 0; drds < 9; drds++) {
        __syncthreads();
        const float4* wsrc = (const float4*)(g_w1oc + (drds << 12));
        #pragma unroll
        for (int j2 = 0; j2 < 4; j2++) {
            int idx = tid + (j2 << 8);               // 1024 float4 = 4096 floats
            ((float4*)ws)[idx] = wsrc[idx];
        }
        __syncthreads();

        int dr = drds / 3, ds = drds - dr * 3;
        int shift = dr * 5 + ds;
        int base[3];
        #pragma unroll
        for (int i = 0; i < 3; i++)
            base[i] = q * 3216 + ((roff[i] + shift) << 7);

        #pragma unroll 2
        for (int op = 0; op < 32; op++) {
            float4 we = *(const float4*)(wrow + (op << 7));       // o = 2op
            float4 wo = *(const float4*)(wrow + (op << 7) + 64);  // o = 2op+1
            u64 we0 = dup2(we.x), we1 = dup2(we.y), we2 = dup2(we.z), we3 = dup2(we.w);
            u64 wo0 = dup2(wo.x), wo1 = dup2(wo.y), wo2 = dup2(wo.z), wo3 = dup2(wo.w);
            #pragma unroll
            for (int i = 0; i < 3; i++) {
                if (i < nrs) {
                    ulonglong2 a = *(const ulonglong2*)&As[base[i] + (op << 2)];
                    fma2(acc[i][0], a.x, we0); fma2(acc[i][1], a.x, we1);
                    fma2(acc[i][2], a.x, we2); fma2(acc[i][3], a.x, we3);
                    fma2(acc[i][0], a.y, wo0); fma2(acc[i][1], a.y, wo1);
                    fma2(acc[i][2], a.y, wo2); fma2(acc[i][3], a.y, wo3);
                }
            }
        }
    }

    float4 s4 = *(const float4*)&g_s1[oc << 2];
    float4 t4 = *(const float4*)&g_t1[oc << 2];
    #pragma unroll
    for (int i = 0; i < 3; i++) {
        if (i < nrs) {
            int rs = rs0 + i;
            float2 v0 = unpack2(acc[i][0]);
            float2 v1 = unpack2(acc[i][1]);
            float2 v2 = unpack2(acc[i][2]);
            float2 v3 = unpack2(acc[i][3]);
            float4 r0, r1;
            r0.x = fmaxf(v0.x * s4.x + t4.x, 0.f);
            r0.y = fmaxf(v1.x * s4.y + t4.y, 0.f);
            r0.z = fmaxf(v2.x * s4.z + t4.z, 0.f);
            r0.w = fmaxf(v3.x * s4.w + t4.w, 0.f);
            r1.x = fmaxf(v0.y * s4.x + t4.x, 0.f);
            r1.y = fmaxf(v1.y * s4.y + t4.y, 0.f);
            r1.z = fmaxf(v2.y * s4.z + t4.z, 0.f);
            r1.w = fmaxf(v3.y * s4.w + t4.w, 0.f);
            *(float4*)&g_A1[(((size_t)(pos0 + 2 * q)     * 9 + rs) << 6) + (oc << 2)] = r0;
            *(float4*)&g_A1[(((size_t)(pos0 + 2 * q + 1) * 9 + rs) << 6) + (oc << 2)] = r1;
        }
    }
}

// ---------------- Conv2: 3x3 -> 1x1, 64->64; BN+ReLU ----------------
// CTA = 32 positions. smem: A1[32][576] (73.7KB) + w chunk [64][68] (17.4KB) -> 2 CTA/SM.
__global__ void __launch_bounds__(256) conv2_kernel()
{
    extern __shared__ float sm[];
    float* A1s = sm;                                 // 18432
    float* ws2 = sm + 18432;                         // 4352
    int pos0 = blockIdx.x << 5;
    int tid = threadIdx.x;

    const float4* src = (const float4*)(g_A1 + ((size_t)pos0 * 576));
    for (int i = tid; i < 4608; i += 256) ((float4*)A1s)[i] = src[i];

    int o3b = tid & 31, g = tid >> 5;                // warp g owns p = g+8i
    u64 acc[4][2];
    #pragma unroll
    for (int i = 0; i < 4; i++) { acc[i][0] = 0; acc[i][1] = 0; }

    for (int jc = 0; jc < 9; jc++) {
        __syncthreads();
        #pragma unroll
        for (int j2 = 0; j2 < 16; j2++) {
            int idx = tid + (j2 << 8);
            ws2[(idx >> 6) * 68 + (idx & 63)] = g_w2tt[(idx >> 6) * 576 + (jc << 6) + (idx & 63)];
        }
        __syncthreads();

        int jbase = jc << 6;
        for (int jj = 0; jj < 64; jj += 4) {
            ulonglong2 wlo = *(const ulonglong2*)&ws2[o3b * 68 + jj];
            ulonglong2 whi = *(const ulonglong2*)&ws2[(o3b + 32) * 68 + jj];
            #pragma unroll
            for (int i = 0; i < 4; i++) {
                int p = g + (i << 3);
                ulonglong2 a = *(const ulonglong2*)&A1s[p * 576 + jbase + jj];
                fma2(acc[i][0], a.x, wlo.x);
                fma2(acc[i][0], a.y, wlo.y);
                fma2(acc[i][1], a.x, whi.x);
                fma2(acc[i][1], a.y, whi.y);
            }
        }
    }

    float sa = g_s2[o3b], ta = g_t2[o3b], sb = g_s2[o3b + 32], tb = g_t2[o3b + 32];
    #pragma unroll
    for (int i = 0; i < 4; i++) {
        int p = pos0 + g + (i << 3);
        float2 va = unpack2(acc[i][0]);
        float2 vb = unpack2(acc[i][1]);
        g_B2[(p << 6) + o3b]      = fmaxf((va.x + va.y) * sa + ta, 0.f);
        g_B2[(p << 6) + o3b + 32] = fmaxf((vb.x + vb.y) * sb + tb, 0.f);
    }
}

// ---------------- GEMM out: 64->144, BN (no ReLU) ----------------
__global__ void __launch_bounds__(256) gemmout_kernel(const float* __restrict__ w_out,
                                                      float* __restrict__ out)
{
    extern __shared__ float sm[];                    // 4160 + 9216 floats
    float* B2t = sm;
    float* ws  = sm + 4160;
    int pos0 = blockIdx.x << 6;
    int tid = threadIdx.x;

    for (int idx = tid; idx < 4096; idx += 256) {
        int p = idx >> 6, cm = idx & 63;
        B2t[cm * 65 + p] = g_B2[(pos0 << 6) + idx];
    }
    for (int idx = tid; idx < 9216; idx += 256) {
        int oc = idx >> 6, cm = idx & 63;
        ws[cm * 144 + oc] = w_out[idx];              // w_out[oc][cm]
    }
    __syncthreads();

    int pl = tid & 63, ocg = tid >> 6;               // ocg block of 36 oc
    u64 acc[18];
    #pragma unroll
    for (int j = 0; j < 18; j++) acc[j] = 0;

    for (int cm = 0; cm < 64; cm++) {
        u64 bv = dup2(B2t[cm * 65 + pl]);
        const ulonglong2* wp = (const ulonglong2*)&ws[cm * 144 + ocg * 36];
        #pragma unroll
        for (int j = 0; j < 9; j++) {
            ulonglong2 w = wp[j];
            fma2(acc[2 * j],     w.x, bv);
            fma2(acc[2 * j + 1], w.y, bv);
        }
    }

    int b = pos0 >> 12, hw0 = pos0 & 4095;
    float* op = out + (size_t)b * 589824 + hw0 + pl;
    #pragma unroll
    for (int j = 0; j < 18; j++) {
        int oc0 = ocg * 36 + 2 * j;
        float2 v = unpack2(acc[j]);
        op[(size_t)oc0 * 4096]       = v.x * g_sout[oc0]     + g_tout[oc0];
        op[(size_t)(oc0 + 1) * 4096] = v.y * g_sout[oc0 + 1] + g_tout[oc0 + 1];
    }
}

// ---------------- launch ----------------
extern "C" void kernel_launch(void* const* d_in, const int* in_sizes, int n_in,
                              void* d_out, int out_size)
{
    (void)in_sizes; (void)n_in; (void)out_size;
    const float* x     = (const float*)d_in[0];
    const float* w_in  = (const float*)d_in[1];
    const float* gin   = (const float*)d_in[2];
    const float* bin   = (const float*)d_in[3];
    const float* min_  = (const float*)d_in[4];
    const float* vin   = (const float*)d_in[5];
    const float* w1    = (const float*)d_in[6];
    const float* g1    = (const float*)d_in[7];
    const float* b1    = (const float*)d_in[8];
    const float* m1    = (const float*)d_in[9];
    const float* v1    = (const float*)d_in[10];
    const float* w2    = (const float*)d_in[11];
    const float* g2    = (const float*)d_in[12];
    const float* b2    = (const float*)d_in[13];
    const float* m2    = (const float*)d_in[14];
    const float* v2    = (const float*)d_in[15];
    const float* w_out = (const float*)d_in[16];
    const float* go    = (const float*)d_in[17];
    const float* bo    = (const float*)d_in[18];
    const float* mo    = (const float*)d_in[19];
    const float* vo    = (const float*)d_in[20];
    float* out = (float*)d_out;

    cudaFuncSetAttribute(gemm1_kernel,   cudaFuncAttributeMaxDynamicSharedMemorySize, 66816);
    cudaFuncSetAttribute(conv1_kernel,   cudaFuncAttributeMaxDynamicSharedMemorySize, 67840);
    cudaFuncSetAttribute(conv2_kernel,   cudaFuncAttributeMaxDynamicSharedMemorySize, 91136);
    cudaFuncSetAttribute(gemmout_kernel, cudaFuncAttributeMaxDynamicSharedMemorySize, 53504);

    prep_kernel<<<144, 256>>>(w_in, gin, bin, min_, vin,
                              w1, g1, b1, m1, v1,
                              w2, g2, b2, m2, v2,
                              go, bo, mo, vo);
    normalize_kernel<<<64, 256>>>(x);
    gemm1_kernel<<<4096, 256, 66816>>>();
    conv1_kernel<<<2048, 256, 67840>>>();
    conv2_kernel<<<512, 256, 91136>>>();
    gemmout_kernel<<<256, 256, 53504>>>(w_out, out);
}